// round 7
// baseline (speedup 1.0000x reference)
#include <cuda_runtime.h>
#include <cuda_fp16.h>
#include <math.h>

#define NMAX 100000
#define EMAX 1600000
#define DIN  128
#define DHID 128
#define DOUT 64

// ----------------------------- scratch (no allocs allowed) ------------------
__device__ __half g_h[(size_t)NMAX * DHID];    // fp16 message buffer (both layers)
__device__ __half g_agg[(size_t)NMAX * DHID];  // layer-1 aggregated output (fp16, relu'd)
__device__ float  g_dinv[NMAX];
__device__ int    g_cnt[NMAX];
__device__ int    g_rowptr[NMAX + 1];
__device__ int    g_cursor[NMAX];
__device__ int    g_csrc[EMAX];
__device__ int    g_bsum[1024];
__device__ __half g_Wt1[DHID * DIN];           // W1^T as [n][k] fp16
__device__ __half g_Wt2[DOUT * DIN];           // W2^T as [n][k] fp16

// ----------------------------- helpers ---------------------------------------
__device__ __forceinline__ unsigned su32(const void* p) {
    return (unsigned)__cvta_generic_to_shared(p);
}
__device__ __forceinline__ void ldsm_x4(unsigned addr, unsigned& r0, unsigned& r1,
                                        unsigned& r2, unsigned& r3) {
    asm volatile("ldmatrix.sync.aligned.m8n8.x4.shared.b16 {%0,%1,%2,%3}, [%4];"
                 : "=r"(r0), "=r"(r1), "=r"(r2), "=r"(r3) : "r"(addr));
}
__device__ __forceinline__ void cpasync16(unsigned daddr, const void* src) {
    asm volatile("cp.async.cg.shared.global [%0], [%1], 16;" :: "r"(daddr), "l"(src));
}
__device__ __forceinline__ unsigned packh2(float a, float b) {
    __half2 p = __floats2half2_rn(a, b);
    return *reinterpret_cast<unsigned*>(&p);
}

// ----------------------------- degree histogram ------------------------------
__global__ void k_hist(const int* __restrict__ dst, int* __restrict__ cnt, int e) {
    int i = blockIdx.x * blockDim.x + threadIdx.x;
    if (i < e) atomicAdd(&cnt[dst[i]], 1);
}

// ----------------------------- CSR build (scan + fill) + dinv ----------------
__global__ void k_scan1(const int* __restrict__ cnt, int* __restrict__ rowptr,
                        int* __restrict__ bsum, float* __restrict__ dinv, int n) {
    __shared__ int sm[256];
    int i = blockIdx.x * 256 + threadIdx.x;
    int v = (i < n) ? cnt[i] : 0;
    if (i < n) dinv[i] = rsqrtf((float)(v + 1));  // +1 self loop
    sm[threadIdx.x] = v;
    __syncthreads();
    for (int off = 1; off < 256; off <<= 1) {
        int t = (threadIdx.x >= off) ? sm[threadIdx.x - off] : 0;
        __syncthreads();
        sm[threadIdx.x] += t;
        __syncthreads();
    }
    if (i < n) rowptr[i] = sm[threadIdx.x] - v;  // exclusive within block
    if (threadIdx.x == 255) bsum[blockIdx.x] = sm[255];
}
__global__ void k_scan2(int* __restrict__ bsum, int nb) {
    __shared__ int sm[1024];
    int t = threadIdx.x;
    int v = (t < nb) ? bsum[t] : 0;
    sm[t] = v;
    __syncthreads();
    for (int off = 1; off < 1024; off <<= 1) {
        int u = (t >= off) ? sm[t - off] : 0;
        __syncthreads();
        sm[t] += u;
        __syncthreads();
    }
    if (t < nb) bsum[t] = sm[t] - v;  // exclusive
}
__global__ void k_scan3(int* __restrict__ rowptr, int* __restrict__ cursor,
                        const int* __restrict__ bsum, int n, int e) {
    int i = blockIdx.x * 256 + threadIdx.x;
    if (i < n) {
        int v = rowptr[i] + bsum[blockIdx.x];
        rowptr[i] = v;
        cursor[i] = v;
    }
    if (i == 0) rowptr[n] = e;
}
__global__ void k_fill(const int* __restrict__ src, const int* __restrict__ dst,
                       int* __restrict__ cursor, int* __restrict__ csrc, int e) {
    int i = blockIdx.x * blockDim.x + threadIdx.x;
    if (i < e) {
        int d = dst[i];
        int pos = atomicAdd(&cursor[d], 1);
        csrc[pos] = src[i];
    }
}

// ---------------- weight transpose + fp16 convert (both layers) ---------------
__global__ void k_convW(const float* __restrict__ W1, __half* __restrict__ Wt1,
                        const float* __restrict__ W2, __half* __restrict__ Wt2) {
    int idx = blockIdx.x * blockDim.x + threadIdx.x;
    const int n1 = DHID * DIN;
    if (idx < n1) {
        int c = idx / DIN, k = idx % DIN;
        Wt1[idx] = __float2half(W1[(size_t)k * DHID + c]);
    } else if (idx < n1 + DOUT * DIN) {
        int j = idx - n1;
        int kk = j / DOUT ? 0 : 0;  // (unused)
        int c = j / DIN, k = j % DIN;
        (void)kk;
        Wt2[j] = __float2half(W2[(size_t)k * DOUT + c]);
    }
}

// ----------------------------- HMMA GEMM (A register-hoisted) ------------------
// H[row] = half( dinv[row] * ( X[row] @ W ) ),  Wt = [n][k] fp16.
// 64 rows/block, 256 thr; warp = m16 x n(DO/2). All A fragment loads for the
// full K=128 are issued up front into registers (MLP ~32/thread), then one
// LDSM+MMA loop. B staged once via cp.async.
template <int DO, typename TIN>
__global__ void __launch_bounds__(256, 2)
k_gemm_mma(const TIN* __restrict__ X, const __half* __restrict__ Wt,
           const float* __restrict__ dinv, __half* __restrict__ H, int n) {
    constexpr int AST = DIN + 8;      // padded B stride in halves
    constexpr int NT  = DO / 16;      // n8 tile pairs per warp (warp covers DO/2)
    constexpr int NP  = NT / 2;       // ldmatrix x4 pairs
    constexpr int KS  = DIN / 16;     // 8 k-steps

    extern __shared__ __half sh[];
    __half (*Bs)[AST] = reinterpret_cast<__half(*)[AST]>(sh);

    const int tid = threadIdx.x, wid = tid >> 5, lane = tid & 31;
    const int mi = wid & 3, nj = wid >> 2;
    const int n0 = nj * (DO / 2);
    const int g = lane >> 2, c = (lane & 3) * 2;
    const int row0 = blockIdx.x * 64;

    // stage B via cp.async (DO x 128 halves, 16B per slot)
    for (int i = tid; i < DO * 16; i += 256) {
        int r = i >> 4, kq = (i & 15) * 8;
        cpasync16(su32(&Bs[r][kq]), Wt + (size_t)r * DIN + kq);
    }
    asm volatile("cp.async.commit_group;");

    // this thread's two A rows (clamped; invalid rows never stored)
    const int r0 = row0 + mi * 16 + g;
    const int r1 = r0 + 8;
    const bool v0 = r0 < n, v1 = r1 < n;
    const TIN* rp0 = X + (size_t)(v0 ? r0 : 0) * DIN;
    const TIN* rp1 = X + (size_t)(v1 ? r1 : 0) * DIN;

    // ---- hoisted A loads: all K=128 fragments up front ----
    unsigned A0[KS], A1[KS], A2[KS], A3[KS];
    if (sizeof(TIN) == 4) {
        const float* f0 = reinterpret_cast<const float*>(rp0);
        const float* f1 = reinterpret_cast<const float*>(rp1);
        float2 x00[KS], x01[KS], x10[KS], x11[KS];
#pragma unroll
        for (int ks = 0; ks < KS; ks++) {
            const int kb = ks * 16 + c;
            x00[ks] = *reinterpret_cast<const float2*>(f0 + kb);
            x01[ks] = *reinterpret_cast<const float2*>(f0 + kb + 8);
            x10[ks] = *reinterpret_cast<const float2*>(f1 + kb);
            x11[ks] = *reinterpret_cast<const float2*>(f1 + kb + 8);
        }
#pragma unroll
        for (int ks = 0; ks < KS; ks++) {
            A0[ks] = packh2(x00[ks].x, x00[ks].y);
            A1[ks] = packh2(x10[ks].x, x10[ks].y);
            A2[ks] = packh2(x01[ks].x, x01[ks].y);
            A3[ks] = packh2(x11[ks].x, x11[ks].y);
        }
    } else {
        const __half* h0 = reinterpret_cast<const __half*>(rp0);
        const __half* h1 = reinterpret_cast<const __half*>(rp1);
#pragma unroll
        for (int ks = 0; ks < KS; ks++) {
            const int kb = ks * 16 + c;
            A0[ks] = *reinterpret_cast<const unsigned*>(h0 + kb);
            A1[ks] = *reinterpret_cast<const unsigned*>(h1 + kb);
            A2[ks] = *reinterpret_cast<const unsigned*>(h0 + kb + 8);
            A3[ks] = *reinterpret_cast<const unsigned*>(h1 + kb + 8);
        }
    }

    asm volatile("cp.async.wait_group 0;");
    __syncthreads();

    float acc[NT][4];
#pragma unroll
    for (int t = 0; t < NT; t++)
#pragma unroll
        for (int q = 0; q < 4; q++) acc[t][q] = 0.f;

    const int lrow = lane & 15;            // ldmatrix row select
    const int lcol = (lane >> 4) * 8;      // ldmatrix col-8 select
    unsigned b_base[NP];
#pragma unroll
    for (int p = 0; p < NP; p++) b_base[p] = su32(&Bs[n0 + p * 16 + lrow][lcol]);

#pragma unroll
    for (int ks = 0; ks < KS; ks++) {
#pragma unroll
        for (int p = 0; p < NP; p++) {
            unsigned b0, b1, b2, b3;
            ldsm_x4(b_base[p] + ks * 32, b0, b1, b2, b3);
            asm volatile(
                "mma.sync.aligned.m16n8k16.row.col.f32.f16.f16.f32 "
                "{%0,%1,%2,%3}, {%4,%5,%6,%7}, {%8,%9}, {%0,%1,%2,%3};"
                : "+f"(acc[2 * p][0]), "+f"(acc[2 * p][1]),
                  "+f"(acc[2 * p][2]), "+f"(acc[2 * p][3])
                : "r"(A0[ks]), "r"(A1[ks]), "r"(A2[ks]), "r"(A3[ks]),
                  "r"(b0), "r"(b2));
            asm volatile(
                "mma.sync.aligned.m16n8k16.row.col.f32.f16.f16.f32 "
                "{%0,%1,%2,%3}, {%4,%5,%6,%7}, {%8,%9}, {%0,%1,%2,%3};"
                : "+f"(acc[2 * p + 1][0]), "+f"(acc[2 * p + 1][1]),
                  "+f"(acc[2 * p + 1][2]), "+f"(acc[2 * p + 1][3])
                : "r"(A0[ks]), "r"(A1[ks]), "r"(A2[ks]), "r"(A3[ks]),
                  "r"(b1), "r"(b3));
        }
    }

    // epilogue: scale by dinv[row], store fp16
    const float dv0 = v0 ? dinv[r0] : 0.f;
    const float dv1 = v1 ? dinv[r1] : 0.f;
#pragma unroll
    for (int t = 0; t < NT; t++) {
        const int col = n0 + t * 8 + c;
        if (v0) {
            __half2 h0 = __floats2half2_rn(acc[t][0] * dv0, acc[t][1] * dv0);
            *reinterpret_cast<__half2*>(H + (size_t)r0 * DO + col) = h0;
        }
        if (v1) {
            __half2 h1 = __floats2half2_rn(acc[t][2] * dv1, acc[t][3] * dv1);
            *reinterpret_cast<__half2*>(H + (size_t)r1 * DO + col) = h1;
        }
    }
}

// ----------------------------- CSR gather aggregation (fp16 in) --------------
// OUT[d] = f( dinv[d] * ( sum_{s in N(d)} H[s] + H[d] ) + bias )
// HOUT: f = relu, stored fp16 (layer 1).  else: identity, stored fp32 (layer 2).
template <int D, bool HOUT>
__global__ void k_gather(const __half* __restrict__ H, const int* __restrict__ rowptr,
                         const int* __restrict__ csrc, const float* __restrict__ dinv,
                         const float* __restrict__ bias, void* __restrict__ OUTv, int n) {
    constexpr int VW = D / 32;  // halves per lane: 4 or 2
    const int w = (blockIdx.x * blockDim.x + threadIdx.x) >> 5;
    const int lane = threadIdx.x & 31;
    if (w >= n) return;

    const int beg = __ldg(&rowptr[w]);
    const int end = __ldg(&rowptr[w + 1]);

    float accA[VW], accB[VW];
#pragma unroll
    for (int c = 0; c < VW; c++) { accA[c] = 0.f; accB[c] = 0.f; }

    auto addrow = [&](int s, float* acc) {
        const __half* hp = H + (size_t)s * D + lane * VW;
        if (VW == 4) {
            uint2 raw = __ldg(reinterpret_cast<const uint2*>(hp));
            float2 f0 = __half22float2(*reinterpret_cast<__half2*>(&raw.x));
            float2 f1 = __half22float2(*reinterpret_cast<__half2*>(&raw.y));
            acc[0] += f0.x; acc[1] += f0.y; acc[2] += f1.x; acc[3] += f1.y;
        } else {
            unsigned raw = __ldg(reinterpret_cast<const unsigned*>(hp));
            float2 f0 = __half22float2(*reinterpret_cast<__half2*>(&raw));
            acc[0] += f0.x; acc[1] += f0.y;
        }
    };

    int j = beg;
    for (; j + 3 < end; j += 4) {
        int s0 = __ldg(&csrc[j]);
        int s1 = __ldg(&csrc[j + 1]);
        int s2 = __ldg(&csrc[j + 2]);
        int s3 = __ldg(&csrc[j + 3]);
        addrow(s0, accA); addrow(s1, accB);
        addrow(s2, accA); addrow(s3, accB);
    }
    for (; j < end; j++) addrow(__ldg(&csrc[j]), accA);
    addrow(w, accB);  // self loop

    const float dv = __ldg(&dinv[w]);
    float val[VW];
#pragma unroll
    for (int c = 0; c < VW; c++) {
        float bb = __ldg(&bias[lane * VW + c]);
        val[c] = fmaf(accA[c] + accB[c], dv, bb);
        if (HOUT) val[c] = fmaxf(val[c], 0.f);
    }

    if (HOUT) {
        __half* O = reinterpret_cast<__half*>(OUTv) + (size_t)w * D + lane * VW;
        if (VW == 4) {
            __half2 p0 = __floats2half2_rn(val[0], val[1]);
            __half2 p1 = __floats2half2_rn(val[2], val[3]);
            uint2 st;
            st.x = *reinterpret_cast<unsigned*>(&p0);
            st.y = *reinterpret_cast<unsigned*>(&p1);
            *reinterpret_cast<uint2*>(O) = st;
        } else {
            *reinterpret_cast<__half2*>(O) = __floats2half2_rn(val[0], val[1]);
        }
    } else {
        float* O = reinterpret_cast<float*>(OUTv) + (size_t)w * D + lane * VW;
        if (VW == 4)
            *reinterpret_cast<float4*>(O) = make_float4(val[0], val[1], val[2], val[3]);
        else
            *reinterpret_cast<float2*>(O) = make_float2(val[0], val[1]);
    }
}

// -----------------------------------------------------------------------------
extern "C" void kernel_launch(void* const* d_in, const int* in_sizes, int n_in,
                              void* d_out, int out_size) {
    const float* x  = (const float*)d_in[0];
    const int*   ei = (const int*)d_in[1];  // [2,E]: src=ei, dst=ei+e
    const float* W1 = (const float*)d_in[2];
    const float* b1 = (const float*)d_in[3];
    const float* W2 = (const float*)d_in[4];
    const float* b2 = (const float*)d_in[5];
    float* out = (float*)d_out;

    const int n = in_sizes[0] / DIN;
    const int e = in_sizes[1] / 2;

    __half *h, *aggh, *Wt1, *Wt2;
    float* dinv;
    int *cnt, *rowptr, *cursor, *csrc, *bsum;
    cudaGetSymbolAddress((void**)&h,      g_h);
    cudaGetSymbolAddress((void**)&aggh,   g_agg);
    cudaGetSymbolAddress((void**)&dinv,   g_dinv);
    cudaGetSymbolAddress((void**)&cnt,    g_cnt);
    cudaGetSymbolAddress((void**)&rowptr, g_rowptr);
    cudaGetSymbolAddress((void**)&cursor, g_cursor);
    cudaGetSymbolAddress((void**)&csrc,   g_csrc);
    cudaGetSymbolAddress((void**)&bsum,   g_bsum);
    cudaGetSymbolAddress((void**)&Wt1,    g_Wt1);
    cudaGetSymbolAddress((void**)&Wt2,    g_Wt2);

    // dynamic smem: B tile only (AST = 136 halves)
    const int SM1 = DHID * 136 * 2;   // 34816B
    const int SM2 = DOUT * 136 * 2;   // 17408B
    cudaFuncSetAttribute(k_gemm_mma<DHID, float>,
                         cudaFuncAttributeMaxDynamicSharedMemorySize, SM1);
    cudaFuncSetAttribute(k_gemm_mma<DOUT, __half>,
                         cudaFuncAttributeMaxDynamicSharedMemorySize, SM2);

    const int TB = 256;
    const int nb = (n + TB - 1) / TB;      // scan blocks
    const int gb = (n + 63) / 64;          // gemm blocks (64 rows each)
    const int ab = (n + 7) / 8;            // gather blocks (8 warps/block)

    // idx0: zero degree counters
    cudaMemsetAsync(cnt, 0, (size_t)n * sizeof(int));
    // idx1: degree histogram
    k_hist<<<(e + TB - 1) / TB, TB>>>(ei + e, cnt, e);
    // idx2: block scan + dinv
    k_scan1<<<nb, TB>>>(cnt, rowptr, bsum, dinv, n);
    // idx3: weight transpose/convert
    const int wtot = DHID * DIN + DOUT * DIN;
    k_convW<<<(wtot + TB - 1) / TB, TB>>>(W1, Wt1, W2, Wt2);
    // idx4: layer-1 GEMM (profiled slot)
    k_gemm_mma<DHID, float><<<gb, 256, SM1>>>(x, Wt1, dinv, h, n);
    // CSR finish
    k_scan2<<<1, 1024>>>(bsum, nb);
    k_scan3<<<nb, TB>>>(rowptr, cursor, bsum, n, e);
    k_fill<<<(e + TB - 1) / TB, TB>>>(ei, ei + e, cursor, csrc, e);
    // layer-1 aggregate (relu + fp16 out), layer-2 GEMM + aggregate
    k_gather<DHID, true><<<ab, 256>>>(h, rowptr, csrc, dinv, b1, aggh, n);
    k_gemm_mma<DOUT, __half><<<gb, 256, SM2>>>(aggh, Wt2, dinv, h, n);
    k_gather<DOUT, false><<<ab, 256>>>(h, rowptr, csrc, dinv, b2, out, n);
}

// round 8
// speedup vs baseline: 1.1442x; 1.1442x over previous
#include <cuda_runtime.h>
#include <cuda_fp16.h>
#include <math.h>

#define NMAX 100000
#define EMAX 1600000
#define DIN  128
#define DHID 128
#define DOUT 64

// ----------------------------- scratch (no allocs allowed) ------------------
__device__ __half g_h[(size_t)NMAX * DHID];    // fp16 message buffer (both layers)
__device__ __half g_agg[(size_t)NMAX * DHID];  // layer-1 aggregated output (fp16, relu'd)
__device__ float  g_dinv[NMAX];
__device__ int    g_cnt[NMAX];
__device__ int    g_rowptr[NMAX + 1];
__device__ int    g_cursor[NMAX];
__device__ int    g_csrc[EMAX];
__device__ int    g_bsum[1024];
__device__ __half g_Wt1[DHID * DIN];           // W1^T as [n][k] fp16
__device__ __half g_Wt2[DOUT * DIN];           // W2^T as [n][k] fp16

// ----------------------------- helpers ---------------------------------------
__device__ __forceinline__ unsigned su32(const void* p) {
    return (unsigned)__cvta_generic_to_shared(p);
}
__device__ __forceinline__ void ldsm_x4(unsigned addr, unsigned& r0, unsigned& r1,
                                        unsigned& r2, unsigned& r3) {
    asm volatile("ldmatrix.sync.aligned.m8n8.x4.shared.b16 {%0,%1,%2,%3}, [%4];"
                 : "=r"(r0), "=r"(r1), "=r"(r2), "=r"(r3) : "r"(addr));
}
__device__ __forceinline__ void cpasync16(unsigned daddr, const void* src) {
    asm volatile("cp.async.cg.shared.global [%0], [%1], 16;" :: "r"(daddr), "l"(src));
}
__device__ __forceinline__ unsigned packh2(float a, float b) {
    __half2 p = __floats2half2_rn(a, b);
    return *reinterpret_cast<unsigned*>(&p);
}

// ----------------------------- degree histogram ------------------------------
__global__ void k_hist(const int* __restrict__ dst, int* __restrict__ cnt, int e) {
    int i = blockIdx.x * blockDim.x + threadIdx.x;
    if (i < e) atomicAdd(&cnt[dst[i]], 1);
}

// ----------------------------- CSR build (scan + fill) + dinv ----------------
__global__ void k_scan1(const int* __restrict__ cnt, int* __restrict__ rowptr,
                        int* __restrict__ bsum, float* __restrict__ dinv, int n) {
    __shared__ int sm[256];
    int i = blockIdx.x * 256 + threadIdx.x;
    int v = (i < n) ? cnt[i] : 0;
    if (i < n) dinv[i] = rsqrtf((float)(v + 1));  // +1 self loop
    sm[threadIdx.x] = v;
    __syncthreads();
    for (int off = 1; off < 256; off <<= 1) {
        int t = (threadIdx.x >= off) ? sm[threadIdx.x - off] : 0;
        __syncthreads();
        sm[threadIdx.x] += t;
        __syncthreads();
    }
    if (i < n) rowptr[i] = sm[threadIdx.x] - v;  // exclusive within block
    if (threadIdx.x == 255) bsum[blockIdx.x] = sm[255];
}
__global__ void k_scan2(int* __restrict__ bsum, int nb) {
    __shared__ int sm[1024];
    int t = threadIdx.x;
    int v = (t < nb) ? bsum[t] : 0;
    sm[t] = v;
    __syncthreads();
    for (int off = 1; off < 1024; off <<= 1) {
        int u = (t >= off) ? sm[t - off] : 0;
        __syncthreads();
        sm[t] += u;
        __syncthreads();
    }
    if (t < nb) bsum[t] = sm[t] - v;  // exclusive
}
__global__ void k_scan3(int* __restrict__ rowptr, int* __restrict__ cursor,
                        const int* __restrict__ bsum, int n, int e) {
    int i = blockIdx.x * 256 + threadIdx.x;
    if (i < n) {
        int v = rowptr[i] + bsum[blockIdx.x];
        rowptr[i] = v;
        cursor[i] = v;
    }
    if (i == 0) rowptr[n] = e;
}
__global__ void k_fill(const int* __restrict__ src, const int* __restrict__ dst,
                       int* __restrict__ cursor, int* __restrict__ csrc, int e) {
    int i = blockIdx.x * blockDim.x + threadIdx.x;
    if (i < e) {
        int d = dst[i];
        int pos = atomicAdd(&cursor[d], 1);
        csrc[pos] = src[i];
    }
}

// ---------------- weight transpose + fp16 convert (both layers) ---------------
__global__ void k_convW(const float* __restrict__ W1, __half* __restrict__ Wt1,
                        const float* __restrict__ W2, __half* __restrict__ Wt2) {
    int idx = blockIdx.x * blockDim.x + threadIdx.x;
    const int n1 = DHID * DIN;
    if (idx < n1) {
        int c = idx / DIN, k = idx % DIN;
        Wt1[idx] = __float2half(W1[(size_t)k * DHID + c]);
    } else if (idx < n1 + DOUT * DIN) {
        int j = idx - n1;
        int c = j / DIN, k = j % DIN;
        Wt2[j] = __float2half(W2[(size_t)k * DOUT + c]);
    }
}

// ------------------- HMMA GEMM (pipelined cp.async A staging) ------------------
// H[row] = half( dinv[row] * ( X[row] @ W ) ),  Wt = [n][k] fp16.
// Each block grid-strides over 64-row tiles with a double-buffered cp.async
// pipeline (tile t+1 streams while tile t computes). All gmem loads are 16B
// coalesced (nL=1). A fragments: fp32 -> conflict-free LDS.64 + pack;
// fp16 -> ldmatrix.x4.  B cp.async-resident per block.
template <int DO, typename TIN>
__global__ void __launch_bounds__(256, 2)
k_gemm_mma(const TIN* __restrict__ X, const __half* __restrict__ Wt,
           const float* __restrict__ dinv, __half* __restrict__ H,
           int n, int ntiles) {
    constexpr int AST = 136;          // row stride (elements): bank-offset 8/row
    constexpr int NT  = DO / 16;      // acc tile pairs (warp covers DO/2 cols)
    constexpr int NP  = NT / 2;       // B ldmatrix.x4 per k-step
    constexpr int KS  = DIN / 16;     // 8 k-steps

    extern __shared__ char sh[];
    __half (*Bs)[AST] = reinterpret_cast<__half(*)[AST]>(sh);
    TIN (*As)[AST] = reinterpret_cast<TIN(*)[AST]>(sh + DO * AST * 2);  // 2 stages x 64 rows

    const int tid = threadIdx.x, wid = tid >> 5, lane = tid & 31;
    const int mi = wid & 3, nj = wid >> 2;
    const int n0 = nj * (DO / 2);
    const int g = lane >> 2, c = (lane & 3) * 2;
    const int lrow = lane & 15, lcol = (lane >> 4) * 8;

    // A tile loader: 64 rows x 128 elems, 16B per slot, rows clamped to n-1
    auto load_A = [&](int tile, int stage) {
        const int row0 = tile * 64;
        if (sizeof(TIN) == 4) {  // 2048 slots of 4 floats
            const float* Xf = reinterpret_cast<const float*>(X);
            for (int i = tid; i < 2048; i += 256) {
                int r = i >> 5, kq = (i & 31) * 4;
                int gr = min(row0 + r, n - 1);
                cpasync16(su32(&As[stage * 64 + r][kq]), Xf + (size_t)gr * DIN + kq);
            }
        } else {                 // 1024 slots of 8 halves
            const __half* Xh = reinterpret_cast<const __half*>(X);
            for (int i = tid; i < 1024; i += 256) {
                int r = i >> 4, kq = (i & 15) * 8;
                int gr = min(row0 + r, n - 1);
                cpasync16(su32(&As[stage * 64 + r][kq]), Xh + (size_t)gr * DIN + kq);
            }
        }
    };

    // group 0: B + first A tile
    for (int i = tid; i < DO * 16; i += 256) {
        int r = i >> 4, kq = (i & 15) * 8;
        cpasync16(su32(&Bs[r][kq]), Wt + (size_t)r * DIN + kq);
    }
    int tile = blockIdx.x;
    if (tile < ntiles) load_A(tile, 0);
    asm volatile("cp.async.commit_group;");

    unsigned b_base[NP];
#pragma unroll
    for (int p = 0; p < NP; p++) b_base[p] = su32(&Bs[n0 + p * 16 + lrow][lcol]);

    int stage = 0;
    for (; tile < ntiles; tile += gridDim.x, stage ^= 1) {
        const int nxt = tile + gridDim.x;
        if (nxt < ntiles) load_A(nxt, stage ^ 1);
        asm volatile("cp.async.commit_group;");
        asm volatile("cp.async.wait_group 1;");
        __syncthreads();

        float acc[NT][4];
#pragma unroll
        for (int t = 0; t < NT; t++)
#pragma unroll
            for (int q = 0; q < 4; q++) acc[t][q] = 0.f;

        const TIN* arow0 = As[stage * 64 + mi * 16 + g];
        const TIN* arow1 = As[stage * 64 + mi * 16 + g + 8];
        const unsigned a_base = su32(&As[stage * 64 + mi * 16 + lrow][lcol]);

#pragma unroll
        for (int ks = 0; ks < KS; ks++) {
            unsigned a0, a1, a2, a3;
            if (sizeof(TIN) == 4) {
                const int kb = ks * 16 + c;
                const float* f0 = reinterpret_cast<const float*>(arow0);
                const float* f1 = reinterpret_cast<const float*>(arow1);
                float2 x00 = *reinterpret_cast<const float2*>(f0 + kb);
                float2 x10 = *reinterpret_cast<const float2*>(f1 + kb);
                float2 x01 = *reinterpret_cast<const float2*>(f0 + kb + 8);
                float2 x11 = *reinterpret_cast<const float2*>(f1 + kb + 8);
                a0 = packh2(x00.x, x00.y);
                a1 = packh2(x10.x, x10.y);
                a2 = packh2(x01.x, x01.y);
                a3 = packh2(x11.x, x11.y);
            } else {
                ldsm_x4(a_base + ks * 32, a0, a1, a2, a3);
            }
#pragma unroll
            for (int p = 0; p < NP; p++) {
                unsigned b0, b1, b2, b3;
                ldsm_x4(b_base[p] + ks * 32, b0, b1, b2, b3);
                asm volatile(
                    "mma.sync.aligned.m16n8k16.row.col.f32.f16.f16.f32 "
                    "{%0,%1,%2,%3}, {%4,%5,%6,%7}, {%8,%9}, {%0,%1,%2,%3};"
                    : "+f"(acc[2 * p][0]), "+f"(acc[2 * p][1]),
                      "+f"(acc[2 * p][2]), "+f"(acc[2 * p][3])
                    : "r"(a0), "r"(a1), "r"(a2), "r"(a3), "r"(b0), "r"(b2));
                asm volatile(
                    "mma.sync.aligned.m16n8k16.row.col.f32.f16.f16.f32 "
                    "{%0,%1,%2,%3}, {%4,%5,%6,%7}, {%8,%9}, {%0,%1,%2,%3};"
                    : "+f"(acc[2 * p + 1][0]), "+f"(acc[2 * p + 1][1]),
                      "+f"(acc[2 * p + 1][2]), "+f"(acc[2 * p + 1][3])
                    : "r"(a0), "r"(a1), "r"(a2), "r"(a3), "r"(b1), "r"(b3));
            }
        }

        // epilogue: scale by dinv[row], store fp16
        const int r0 = tile * 64 + mi * 16 + g;
        const int r1 = r0 + 8;
        const bool v0 = r0 < n, v1 = r1 < n;
        const float dv0 = v0 ? dinv[r0] : 0.f;
        const float dv1 = v1 ? dinv[r1] : 0.f;
#pragma unroll
        for (int t = 0; t < NT; t++) {
            const int col = n0 + t * 8 + c;
            if (v0) {
                __half2 h0 = __floats2half2_rn(acc[t][0] * dv0, acc[t][1] * dv0);
                *reinterpret_cast<__half2*>(H + (size_t)r0 * DO + col) = h0;
            }
            if (v1) {
                __half2 h1 = __floats2half2_rn(acc[t][2] * dv1, acc[t][3] * dv1);
                *reinterpret_cast<__half2*>(H + (size_t)r1 * DO + col) = h1;
            }
        }
        __syncthreads();  // compute done before next issue overwrites this stage
    }
    asm volatile("cp.async.wait_group 0;");
}

// ----------------------------- CSR gather aggregation (fp16 in) --------------
// OUT[d] = f( dinv[d] * ( sum_{s in N(d)} H[s] + H[d] ) + bias )
// HOUT: f = relu, stored fp16 (layer 1).  else: identity, stored fp32 (layer 2).
template <int D, bool HOUT>
__global__ void k_gather(const __half* __restrict__ H, const int* __restrict__ rowptr,
                         const int* __restrict__ csrc, const float* __restrict__ dinv,
                         const float* __restrict__ bias, void* __restrict__ OUTv, int n) {
    constexpr int VW = D / 32;  // halves per lane: 4 or 2
    const int w = (blockIdx.x * blockDim.x + threadIdx.x) >> 5;
    const int lane = threadIdx.x & 31;
    if (w >= n) return;

    const int beg = __ldg(&rowptr[w]);
    const int end = __ldg(&rowptr[w + 1]);

    float accA[VW], accB[VW];
#pragma unroll
    for (int c = 0; c < VW; c++) { accA[c] = 0.f; accB[c] = 0.f; }

    auto addrow = [&](int s, float* acc) {
        const __half* hp = H + (size_t)s * D + lane * VW;
        if (VW == 4) {
            uint2 raw = __ldg(reinterpret_cast<const uint2*>(hp));
            float2 f0 = __half22float2(*reinterpret_cast<__half2*>(&raw.x));
            float2 f1 = __half22float2(*reinterpret_cast<__half2*>(&raw.y));
            acc[0] += f0.x; acc[1] += f0.y; acc[2] += f1.x; acc[3] += f1.y;
        } else {
            unsigned raw = __ldg(reinterpret_cast<const unsigned*>(hp));
            float2 f0 = __half22float2(*reinterpret_cast<__half2*>(&raw));
            acc[0] += f0.x; acc[1] += f0.y;
        }
    };

    int j = beg;
    for (; j + 3 < end; j += 4) {
        int s0 = __ldg(&csrc[j]);
        int s1 = __ldg(&csrc[j + 1]);
        int s2 = __ldg(&csrc[j + 2]);
        int s3 = __ldg(&csrc[j + 3]);
        addrow(s0, accA); addrow(s1, accB);
        addrow(s2, accA); addrow(s3, accB);
    }
    for (; j < end; j++) addrow(__ldg(&csrc[j]), accA);
    addrow(w, accB);  // self loop

    const float dv = __ldg(&dinv[w]);
    float val[VW];
#pragma unroll
    for (int c = 0; c < VW; c++) {
        float bb = __ldg(&bias[lane * VW + c]);
        val[c] = fmaf(accA[c] + accB[c], dv, bb);
        if (HOUT) val[c] = fmaxf(val[c], 0.f);
    }

    if (HOUT) {
        __half* O = reinterpret_cast<__half*>(OUTv) + (size_t)w * D + lane * VW;
        if (VW == 4) {
            __half2 p0 = __floats2half2_rn(val[0], val[1]);
            __half2 p1 = __floats2half2_rn(val[2], val[3]);
            uint2 st;
            st.x = *reinterpret_cast<unsigned*>(&p0);
            st.y = *reinterpret_cast<unsigned*>(&p1);
            *reinterpret_cast<uint2*>(O) = st;
        } else {
            *reinterpret_cast<__half2*>(O) = __floats2half2_rn(val[0], val[1]);
        }
    } else {
        float* O = reinterpret_cast<float*>(OUTv) + (size_t)w * D + lane * VW;
        if (VW == 4)
            *reinterpret_cast<float4*>(O) = make_float4(val[0], val[1], val[2], val[3]);
        else
            *reinterpret_cast<float2*>(O) = make_float2(val[0], val[1]);
    }
}

// -----------------------------------------------------------------------------
extern "C" void kernel_launch(void* const* d_in, const int* in_sizes, int n_in,
                              void* d_out, int out_size) {
    const float* x  = (const float*)d_in[0];
    const int*   ei = (const int*)d_in[1];  // [2,E]: src=ei, dst=ei+e
    const float* W1 = (const float*)d_in[2];
    const float* b1 = (const float*)d_in[3];
    const float* W2 = (const float*)d_in[4];
    const float* b2 = (const float*)d_in[5];
    float* out = (float*)d_out;

    const int n = in_sizes[0] / DIN;
    const int e = in_sizes[1] / 2;

    __half *h, *aggh, *Wt1, *Wt2;
    float* dinv;
    int *cnt, *rowptr, *cursor, *csrc, *bsum;
    cudaGetSymbolAddress((void**)&h,      g_h);
    cudaGetSymbolAddress((void**)&aggh,   g_agg);
    cudaGetSymbolAddress((void**)&dinv,   g_dinv);
    cudaGetSymbolAddress((void**)&cnt,    g_cnt);
    cudaGetSymbolAddress((void**)&rowptr, g_rowptr);
    cudaGetSymbolAddress((void**)&cursor, g_cursor);
    cudaGetSymbolAddress((void**)&csrc,   g_csrc);
    cudaGetSymbolAddress((void**)&bsum,   g_bsum);
    cudaGetSymbolAddress((void**)&Wt1,    g_Wt1);
    cudaGetSymbolAddress((void**)&Wt2,    g_Wt2);

    // dynamic smem: B (DO x 136 halves) + 2 A stages (64 x 136 TIN)
    const int SM1 = DHID * 136 * 2 + 2 * 64 * 136 * 4;  // 34816 + 69632 = 104448
    const int SM2 = DOUT * 136 * 2 + 2 * 64 * 136 * 2;  // 17408 + 34816 = 52224
    cudaFuncSetAttribute(k_gemm_mma<DHID, float>,
                         cudaFuncAttributeMaxDynamicSharedMemorySize, SM1);
    cudaFuncSetAttribute(k_gemm_mma<DOUT, __half>,
                         cudaFuncAttributeMaxDynamicSharedMemorySize, SM2);

    const int TB = 256;
    const int nb = (n + TB - 1) / TB;      // scan blocks
    const int ntiles = (n + 63) / 64;      // gemm tiles (64 rows each)
    const int GG = 296;                    // gemm grid (2 blocks/SM)
    const int gemm_grid = ntiles < GG ? ntiles : GG;
    const int ab = (n + 7) / 8;            // gather blocks (8 warps/block)

    // idx0: zero degree counters
    cudaMemsetAsync(cnt, 0, (size_t)n * sizeof(int));
    // idx1: degree histogram
    k_hist<<<(e + TB - 1) / TB, TB>>>(ei + e, cnt, e);
    // idx2: block scan + dinv
    k_scan1<<<nb, TB>>>(cnt, rowptr, bsum, dinv, n);
    // idx3: weight transpose/convert
    const int wtot = DHID * DIN + DOUT * DIN;
    k_convW<<<(wtot + TB - 1) / TB, TB>>>(W1, Wt1, W2, Wt2);
    // idx4: layer-1 GEMM (profiled slot)
    k_gemm_mma<DHID, float><<<gemm_grid, 256, SM1>>>(x, Wt1, dinv, h, n, ntiles);
    // CSR finish
    k_scan2<<<1, 1024>>>(bsum, nb);
    k_scan3<<<nb, TB>>>(rowptr, cursor, bsum, n, e);
    k_fill<<<(e + TB - 1) / TB, TB>>>(ei, ei + e, cursor, csrc, e);
    // layer-1 aggregate (relu + fp16 out), layer-2 GEMM + aggregate
    k_gather<DHID, true><<<ab, 256>>>(h, rowptr, csrc, dinv, b1, aggh, n);
    k_gemm_mma<DOUT, __half><<<gemm_grid, 256, SM2>>>(aggh, Wt2, dinv, h, n, ntiles);
    k_gather<DOUT, false><<<ab, 256>>>(h, rowptr, csrc, dinv, b2, out, n);
}